// round 4
// baseline (speedup 1.0000x reference)
#include <cuda_runtime.h>
#include <cuda_bf16.h>
#include <cstdint>
#include <math.h>

// ---------------- problem constants ----------------
#define BB 2
#define TT 2048
#define DM 2048
#define NH 16
#define NKV 4
#define DK 128
#define NREP 4

// ---------------- scratch (no allocs allowed) ----------------
__device__ float g_Q[BB*TT*DM];        // 32MB
__device__ float g_K[BB*TT*NKV*DK];    // 8MB
__device__ float g_V[BB*TT*NKV*DK];    // 8MB
__device__ float g_O[BB*TT*DM];        // 32MB

// ---------------- mma helper (tf32 m16n8k8) ----------------
__device__ __forceinline__ void mma_tf32(float* c, const uint32_t* a, const uint32_t* b) {
    asm volatile(
        "mma.sync.aligned.m16n8k8.row.col.f32.tf32.tf32.f32 "
        "{%0,%1,%2,%3}, {%4,%5,%6,%7}, {%8,%9}, {%0,%1,%2,%3};\n"
        : "+f"(c[0]), "+f"(c[1]), "+f"(c[2]), "+f"(c[3])
        : "r"(a[0]), "r"(a[1]), "r"(a[2]), "r"(a[3]), "r"(b[0]), "r"(b[1]));
}
// round-to-nearest tf32 conversion (unbiased; raw-bit passing truncates and biases)
__device__ __forceinline__ uint32_t ftf(float x) {
    uint32_t u;
    asm("cvt.rna.tf32.f32 %0, %1;" : "=r"(u) : "f"(x));
    return u;
}

__device__ __forceinline__ void cp16(float* dst, const float* src) {
    uint32_t d = (uint32_t)__cvta_generic_to_shared(dst);
    asm volatile("cp.async.ca.shared.global [%0], [%1], 16;\n" :: "r"(d), "l"(src));
}
#define CP_COMMIT()  asm volatile("cp.async.commit_group;\n" ::: "memory")
#define CP_WAIT1()   asm volatile("cp.async.wait_group 1;\n" ::: "memory")
#define CP_WAIT0()   asm volatile("cp.async.wait_group 0;\n" ::: "memory")

// ============================================================
// GEMM (NT): C[M,N] = A[M,K] * B[N,K]^T  — tf32 mma, 128x128x16
// ============================================================
#define GBM 128
#define GBN 128
#define GBK 16
#define GLD 20   // smem row stride (floats): bank = (20q + c) mod 32 bijective

__global__ __launch_bounds__(256, 2)
void gemm_nt_tf32(const float* __restrict__ A, const float* __restrict__ B,
                  float* __restrict__ C, int M, int N, int K)
{
    __shared__ float As[2][GBM * GLD];
    __shared__ float Bs[2][GBN * GLD];

    const int tid  = threadIdx.x;
    const int lane = tid & 31;
    const int w    = tid >> 5;
    const int wm   = (w >> 2) * 64;   // warp m offset (0 / 64)
    const int wn   = (w & 3) * 32;    // warp n offset (0..96)
    const int m0   = blockIdx.y * GBM;
    const int n0   = blockIdx.x * GBN;

    const float* Ab = A + (size_t)m0 * K;
    const float* Bb = B + (size_t)n0 * K;

    const int ar0 = tid >> 2;        // 0..63
    const int ac  = (tid & 3) * 4;   // 0,4,8,12

    auto load_tile = [&](int st, int kt) {
        const int koff = kt * GBK;
        #pragma unroll
        for (int half = 0; half < 2; half++) {
            const int rw = ar0 + half * 64;
            cp16(&As[st][rw * GLD + ac], Ab + (size_t)rw * K + koff + ac);
            cp16(&Bs[st][rw * GLD + ac], Bb + (size_t)rw * K + koff + ac);
        }
        CP_COMMIT();
    };

    float acc[4][4][4];
    #pragma unroll
    for (int i = 0; i < 4; i++)
        #pragma unroll
        for (int j = 0; j < 4; j++)
            #pragma unroll
            for (int k = 0; k < 4; k++) acc[i][j][k] = 0.f;

    const int r  = lane >> 2;
    const int cq = lane & 3;
    const int nk = K / GBK;

    load_tile(0, 0);

    for (int kt = 0; kt < nk; kt++) {
        const int s = kt & 1;
        if (kt + 1 < nk) { load_tile(1 - s, kt + 1); CP_WAIT1(); }
        else             { CP_WAIT0(); }
        __syncthreads();

        #pragma unroll
        for (int ks = 0; ks < 2; ks++) {
            const int kb = ks * 8;
            uint32_t af[4][4], bf[4][2];
            #pragma unroll
            for (int mi = 0; mi < 4; mi++) {
                const float* p = &As[s][(wm + mi * 16 + r) * GLD + kb + cq];
                af[mi][0] = ftf(p[0]);
                af[mi][1] = ftf(p[8 * GLD]);
                af[mi][2] = ftf(p[4]);
                af[mi][3] = ftf(p[8 * GLD + 4]);
            }
            #pragma unroll
            for (int ni = 0; ni < 4; ni++) {
                const float* p = &Bs[s][(wn + ni * 8 + r) * GLD + kb + cq];
                bf[ni][0] = ftf(p[0]);
                bf[ni][1] = ftf(p[4]);
            }
            #pragma unroll
            for (int mi = 0; mi < 4; mi++)
                #pragma unroll
                for (int ni = 0; ni < 4; ni++)
                    mma_tf32(acc[mi][ni], af[mi], bf[ni]);
        }
        __syncthreads();
    }

    // epilogue
    #pragma unroll
    for (int mi = 0; mi < 4; mi++) {
        const int row0 = m0 + wm + mi * 16 + r;
        #pragma unroll
        for (int ni = 0; ni < 4; ni++) {
            const int col = n0 + wn + ni * 8 + cq * 2;
            float* Cp = C + (size_t)row0 * N + col;
            Cp[0] = acc[mi][ni][0];
            Cp[1] = acc[mi][ni][1];
            float* Cq = C + (size_t)(row0 + 8) * N + col;
            Cq[0] = acc[mi][ni][2];
            Cq[1] = acc[mi][ni][3];
        }
    }
}

// ============================================================
// RoPE (in-place).  NOTE: the reference broadcasts the cos/sin
// tables over the HEAD axis (cos[None, :H, None, :] where axis 1
// is heads after the transpose), so the rotation angle is
//   theta = head_index * freq[d]   (time-independent!)
// ============================================================
__global__ void rope_kernel(float* __restrict__ buf, int n_heads)
{
    const int idx = blockIdx.x * blockDim.x + threadIdx.x;
    const int total = BB * TT * n_heads * 64;
    if (idx >= total) return;
    const int d   = idx & 63;
    const int h   = (idx >> 6) % n_heads;
    const int row = idx / (64 * n_heads);   // b*T + t

    const float freq = (d < 32) ? powf(1e-4f, (float)d * (1.0f / 31.0f)) : 0.0f;
    const float th = (float)h * freq;   // HEAD index, per reference broadcast
    float s, c;
    sincosf(th, &s, &c);

    float* p = buf + (size_t)row * (n_heads * DK) + h * DK + d;
    const float x1 = p[0], x2 = p[64];
    p[0]  =  x1 * c + x2 * s;
    p[64] = -x1 * s + x2 * c;
}

// ============================================================
// Flash attention (causal, GQA) — tf32 mma, online softmax
// one CTA per (qtile=64, head, batch)
// ============================================================
#define ATQ 64
#define ATK 64
#define QLD 136   // stride for Qs/Ks/Vs
#define SLD 68    // stride for Ss

#define ATT_SMEM ((3 * ATQ * QLD + ATQ * SLD + 3 * ATQ) * 4)

__global__ __launch_bounds__(256, 1)
void attn_kernel(const float* __restrict__ Q, const float* __restrict__ K,
                 const float* __restrict__ V, float* __restrict__ O)
{
    extern __shared__ float sm[];
    float* Qs = sm;                    // 64 x 136
    float* Ks = Qs + ATQ * QLD;        // 64 x 136
    float* Vs = Ks + ATK * QLD;        // 64 x 136
    float* Ss = Vs + ATK * QLD;        // 64 x 68
    float* rm = Ss + ATQ * SLD;        // 64
    float* rl = rm + ATQ;              // 64
    float* rc = rl + ATQ;              // 64

    const int tid  = threadIdx.x;
    const int lane = tid & 31;
    const int w    = tid >> 5;
    const int qt = blockIdx.x, h = blockIdx.y, b = blockIdx.z;
    const int q0 = qt * ATQ;
    const int kvh = h >> 2;

    const float* Qg = Q + ((size_t)(b * TT + q0)) * DM + h * DK;
    const float* Kg = K + (size_t)(b * TT) * (NKV * DK) + kvh * DK;
    const float* Vg = V + (size_t)(b * TT) * (NKV * DK) + kvh * DK;

    // load Q tile (64 x 128)
    #pragma unroll
    for (int i = 0; i < 8; i++) {
        const int id = tid + i * 256;
        const int row = id >> 5, c4 = (id & 31) << 2;
        *(float4*)(Qs + row * QLD + c4) = *(const float4*)(Qg + (size_t)row * DM + c4);
    }
    if (tid < ATQ) { rm[tid] = -1e30f; rl[tid] = 0.f; }

    float o[8][4];
    #pragma unroll
    for (int i = 0; i < 8; i++)
        #pragma unroll
        for (int j = 0; j < 4; j++) o[i][j] = 0.f;

    const int wq  = (w >> 1) * 16;  // warp q-row offset (shared by QK & PV)
    const int wn2 = w & 1;
    const int r  = lane >> 2;
    const int cq = lane & 3;
    const float sscale = 0.08838834764831845f;  // 1/sqrt(128)

    for (int j = 0; j <= qt; j++) {
        // load K/V tile (64 x 128 each)
        const float* Kt = Kg + (size_t)(j * ATK) * (NKV * DK);
        const float* Vt = Vg + (size_t)(j * ATK) * (NKV * DK);
        #pragma unroll
        for (int i = 0; i < 8; i++) {
            const int id = tid + i * 256;
            const int row = id >> 5, c4 = (id & 31) << 2;
            *(float4*)(Ks + row * QLD + c4) = *(const float4*)(Kt + (size_t)row * (NKV * DK) + c4);
            *(float4*)(Vs + row * QLD + c4) = *(const float4*)(Vt + (size_t)row * (NKV * DK) + c4);
        }
        __syncthreads();

        // ---- S = Q * K^T (warp: 16q x 32k) ----
        float sacc[4][4];
        #pragma unroll
        for (int i = 0; i < 4; i++)
            #pragma unroll
            for (int k2 = 0; k2 < 4; k2++) sacc[i][k2] = 0.f;

        #pragma unroll
        for (int ks = 0; ks < 16; ks++) {
            const int kb = ks * 8;
            uint32_t af[4];
            const float* p = Qs + (wq + r) * QLD + kb + cq;
            af[0] = ftf(p[0]);
            af[1] = ftf(p[8 * QLD]);
            af[2] = ftf(p[4]);
            af[3] = ftf(p[8 * QLD + 4]);
            #pragma unroll
            for (int ni = 0; ni < 4; ni++) {
                const float* pb = Ks + (wn2 * 32 + ni * 8 + r) * QLD + kb + cq;
                uint32_t bf[2] = { ftf(pb[0]), ftf(pb[4]) };
                mma_tf32(sacc[ni], af, bf);
            }
        }

        // ---- scale + causal mask + store to Ss ----
        #pragma unroll
        for (int ni = 0; ni < 4; ni++) {
            const int col = wn2 * 32 + ni * 8 + cq * 2;
            const int kg  = j * ATK + col;
            const int rq0 = q0 + wq + r;
            const int rq1 = rq0 + 8;
            float v0 = sacc[ni][0] * sscale; if (kg     > rq0) v0 = -1e30f;
            float v1 = sacc[ni][1] * sscale; if (kg + 1 > rq0) v1 = -1e30f;
            float v2 = sacc[ni][2] * sscale; if (kg     > rq1) v2 = -1e30f;
            float v3 = sacc[ni][3] * sscale; if (kg + 1 > rq1) v3 = -1e30f;
            Ss[(wq + r) * SLD + col]         = v0;
            Ss[(wq + r) * SLD + col + 1]     = v1;
            Ss[(wq + r + 8) * SLD + col]     = v2;
            Ss[(wq + r + 8) * SLD + col + 1] = v3;
        }
        __syncthreads();

        // ---- online softmax (4 threads / row) ----
        {
            const int row = tid >> 2, seg = tid & 3;
            float* Sp = Ss + row * SLD + seg * 16;
            float mx = -1e30f;
            #pragma unroll
            for (int i = 0; i < 16; i++) mx = fmaxf(mx, Sp[i]);
            mx = fmaxf(mx, __shfl_xor_sync(0xffffffffu, mx, 1));
            mx = fmaxf(mx, __shfl_xor_sync(0xffffffffu, mx, 2));
            const float mold = rm[row];
            const float mnew = fmaxf(mold, mx);
            float sum = 0.f;
            #pragma unroll
            for (int i = 0; i < 16; i++) {
                const float p2 = __expf(Sp[i] - mnew);
                Sp[i] = p2;
                sum += p2;
            }
            sum += __shfl_xor_sync(0xffffffffu, sum, 1);
            sum += __shfl_xor_sync(0xffffffffu, sum, 2);
            if (seg == 0) {
                const float corr = __expf(mold - mnew);
                rl[row] = rl[row] * corr + sum;
                rc[row] = corr;
                rm[row] = mnew;
            }
        }
        __syncthreads();

        // ---- rescale O, then O += P * V (warp: 16q x 64d) ----
        {
            const float c0 = rc[wq + r];
            const float c1 = rc[wq + r + 8];
            #pragma unroll
            for (int ni = 0; ni < 8; ni++) {
                o[ni][0] *= c0; o[ni][1] *= c0;
                o[ni][2] *= c1; o[ni][3] *= c1;
            }
        }
        #pragma unroll
        for (int ks = 0; ks < 8; ks++) {
            const int kb = ks * 8;
            uint32_t af[4];
            const float* p = Ss + (wq + r) * SLD + kb + cq;
            af[0] = ftf(p[0]);
            af[1] = ftf(p[8 * SLD]);
            af[2] = ftf(p[4]);
            af[3] = ftf(p[8 * SLD + 4]);
            #pragma unroll
            for (int ni = 0; ni < 8; ni++) {
                const float* pb = Vs + (kb + cq) * QLD + wn2 * 64 + ni * 8 + r;
                uint32_t bf[2] = { ftf(pb[0]), ftf(pb[4 * QLD]) };
                mma_tf32(o[ni], af, bf);
            }
        }
        __syncthreads();
    }

    // ---- normalize + write out ----
    const float inv0 = 1.f / rl[wq + r];
    const float inv1 = 1.f / rl[wq + r + 8];
    #pragma unroll
    for (int ni = 0; ni < 8; ni++) {
        const int col = h * DK + wn2 * 64 + ni * 8 + cq * 2;
        const size_t row0 = (size_t)(b * TT + q0 + wq + r);
        O[row0 * DM + col]           = o[ni][0] * inv0;
        O[row0 * DM + col + 1]       = o[ni][1] * inv0;
        O[(row0 + 8) * DM + col]     = o[ni][2] * inv1;
        O[(row0 + 8) * DM + col + 1] = o[ni][3] * inv1;
    }
}

// ============================================================
// launch
// ============================================================
extern "C" void kernel_launch(void* const* d_in, const int* in_sizes, int n_in,
                              void* d_out, int out_size)
{
    const float* x  = (const float*)d_in[0];
    const float* wq = (const float*)d_in[1];
    const float* wk = (const float*)d_in[2];
    const float* wv = (const float*)d_in[3];
    const float* wo = (const float*)d_in[4];
    float* out = (float*)d_out;

    void *pQ, *pK, *pV, *pO;
    cudaGetSymbolAddress(&pQ, g_Q);
    cudaGetSymbolAddress(&pK, g_K);
    cudaGetSymbolAddress(&pV, g_V);
    cudaGetSymbolAddress(&pO, g_O);
    float* gQ = (float*)pQ;
    float* gK = (float*)pK;
    float* gV = (float*)pV;
    float* gO = (float*)pO;

    cudaFuncSetAttribute(attn_kernel, cudaFuncAttributeMaxDynamicSharedMemorySize, ATT_SMEM);

    const int M = BB * TT;  // 4096

    // QKV projections
    gemm_nt_tf32<<<dim3(DM / GBN, M / GBM), 256>>>(x, wq, gQ, M, DM, DM);
    gemm_nt_tf32<<<dim3((NKV * DK) / GBN, M / GBM), 256>>>(x, wk, gK, M, NKV * DK, DM);
    gemm_nt_tf32<<<dim3((NKV * DK) / GBN, M / GBM), 256>>>(x, wv, gV, M, NKV * DK, DM);

    // RoPE (angle depends on head index, per reference broadcast quirk)
    {
        int nq = BB * TT * NH * 64;
        rope_kernel<<<(nq + 255) / 256, 256>>>(gQ, NH);
        int nk = BB * TT * NKV * 64;
        rope_kernel<<<(nk + 255) / 256, 256>>>(gK, NKV);
    }

    // Attention
    attn_kernel<<<dim3(TT / ATQ, NH, BB), 256, ATT_SMEM>>>(gQ, gK, gV, gO);

    // Output projection
    gemm_nt_tf32<<<dim3(DM / GBN, M / GBM), 256>>>(gO, wo, out, M, DM, DM);
}

// round 14
// speedup vs baseline: 1.0271x; 1.0271x over previous
#include <cuda_runtime.h>
#include <cuda_bf16.h>
#include <cstdint>
#include <math.h>

// ---------------- problem constants ----------------
#define BB 2
#define TT 2048
#define DM 2048
#define NH 16
#define NKV 4
#define DK 128
#define NREP 4

// ---------------- scratch (no allocs allowed) ----------------
__device__ float g_Q[BB*TT*DM];        // 32MB
__device__ float g_K[BB*TT*NKV*DK];    // 8MB
__device__ float g_V[BB*TT*NKV*DK];    // 8MB
__device__ float g_O[BB*TT*DM];        // 32MB
__device__ float g_WQ[NH*DK*DM];       // 16MB rotated wq
__device__ float g_WK[NKV*DK*DM];      // 4MB rotated wk

// ---------------- mma helper (tf32 m16n8k8) ----------------
__device__ __forceinline__ void mma_tf32(float* c, const uint32_t* a, const uint32_t* b) {
    asm volatile(
        "mma.sync.aligned.m16n8k8.row.col.f32.tf32.tf32.f32 "
        "{%0,%1,%2,%3}, {%4,%5,%6,%7}, {%8,%9}, {%0,%1,%2,%3};\n"
        : "+f"(c[0]), "+f"(c[1]), "+f"(c[2]), "+f"(c[3])
        : "r"(a[0]), "r"(a[1]), "r"(a[2]), "r"(a[3]), "r"(b[0]), "r"(b[1]));
}
// round-to-nearest tf32 conversion (unbiased)
__device__ __forceinline__ uint32_t ftf(float x) {
    uint32_t u;
    asm("cvt.rna.tf32.f32 %0, %1;" : "=r"(u) : "f"(x));
    return u;
}

__device__ __forceinline__ void cp16(float* dst, const float* src) {
    uint32_t d = (uint32_t)__cvta_generic_to_shared(dst);
    asm volatile("cp.async.ca.shared.global [%0], [%1], 16;\n" :: "r"(d), "l"(src));
}
#define CP_COMMIT()  asm volatile("cp.async.commit_group;\n" ::: "memory")
#define CP_WAIT1()   asm volatile("cp.async.wait_group 1;\n" ::: "memory")
#define CP_WAIT0()   asm volatile("cp.async.wait_group 0;\n" ::: "memory")

// ============================================================
// Weight pre-rotation: RoPE angle = head_index * freq[d] is
// time-independent, so fold the rotation into wq/wk rows.
//   wr[h*128+d]    =  c*w[h*128+d] + s*w[h*128+d+64]
//   wr[h*128+d+64] = -s*w[h*128+d] + c*w[h*128+d+64]
// ============================================================
__global__ void rot_weights(const float* __restrict__ w, float* __restrict__ wr)
{
    const int idx = blockIdx.x * blockDim.x + threadIdx.x;
    const int k = idx & (DM - 1);
    const int d = (idx >> 11) & 63;
    const int h = idx >> 17;          // caller sizes grid exactly

    const float freq = (d < 32) ? powf(1e-4f, (float)d * (1.0f / 31.0f)) : 0.0f;
    float s, c;
    sincosf((float)h * freq, &s, &c);

    const size_t r1 = ((size_t)(h * DK + d)) * DM + k;
    const size_t r2 = ((size_t)(h * DK + d + 64)) * DM + k;
    const float a = w[r1], b = w[r2];
    wr[r1] =  a * c + b * s;
    wr[r2] = -a * s + b * c;
}

// ============================================================
// GEMM (NT): C[M,N] = A[M,K] * B[N,K]^T  — tf32 mma, 128x128x16
// ============================================================
#define GBM 128
#define GBN 128
#define GBK 16
#define GLD 20

__global__ __launch_bounds__(256, 2)
void gemm_nt_tf32(const float* __restrict__ A, const float* __restrict__ B,
                  float* __restrict__ C, int M, int N, int K)
{
    __shared__ float As[2][GBM * GLD];
    __shared__ float Bs[2][GBN * GLD];

    const int tid  = threadIdx.x;
    const int lane = tid & 31;
    const int w    = tid >> 5;
    const int wm   = (w >> 2) * 64;
    const int wn   = (w & 3) * 32;
    const int m0   = blockIdx.y * GBM;
    const int n0   = blockIdx.x * GBN;

    const float* Ab = A + (size_t)m0 * K;
    const float* Bb = B + (size_t)n0 * K;

    const int ar0 = tid >> 2;
    const int ac  = (tid & 3) * 4;

    auto load_tile = [&](int st, int kt) {
        const int koff = kt * GBK;
        #pragma unroll
        for (int half = 0; half < 2; half++) {
            const int rw = ar0 + half * 64;
            cp16(&As[st][rw * GLD + ac], Ab + (size_t)rw * K + koff + ac);
            cp16(&Bs[st][rw * GLD + ac], Bb + (size_t)rw * K + koff + ac);
        }
        CP_COMMIT();
    };

    float acc[4][4][4];
    #pragma unroll
    for (int i = 0; i < 4; i++)
        #pragma unroll
        for (int j = 0; j < 4; j++)
            #pragma unroll
            for (int k = 0; k < 4; k++) acc[i][j][k] = 0.f;

    const int r  = lane >> 2;
    const int cq = lane & 3;
    const int nk = K / GBK;

    load_tile(0, 0);

    for (int kt = 0; kt < nk; kt++) {
        const int s = kt & 1;
        if (kt + 1 < nk) { load_tile(1 - s, kt + 1); CP_WAIT1(); }
        else             { CP_WAIT0(); }
        __syncthreads();

        #pragma unroll
        for (int ks = 0; ks < 2; ks++) {
            const int kb = ks * 8;
            uint32_t af[4][4], bf[4][2];
            #pragma unroll
            for (int mi = 0; mi < 4; mi++) {
                const float* p = &As[s][(wm + mi * 16 + r) * GLD + kb + cq];
                af[mi][0] = ftf(p[0]);
                af[mi][1] = ftf(p[8 * GLD]);
                af[mi][2] = ftf(p[4]);
                af[mi][3] = ftf(p[8 * GLD + 4]);
            }
            #pragma unroll
            for (int ni = 0; ni < 4; ni++) {
                const float* p = &Bs[s][(wn + ni * 8 + r) * GLD + kb + cq];
                bf[ni][0] = ftf(p[0]);
                bf[ni][1] = ftf(p[4]);
            }
            #pragma unroll
            for (int mi = 0; mi < 4; mi++)
                #pragma unroll
                for (int ni = 0; ni < 4; ni++)
                    mma_tf32(acc[mi][ni], af[mi], bf[ni]);
        }
        __syncthreads();
    }

    #pragma unroll
    for (int mi = 0; mi < 4; mi++) {
        const int row0 = m0 + wm + mi * 16 + r;
        #pragma unroll
        for (int ni = 0; ni < 4; ni++) {
            const int col = n0 + wn + ni * 8 + cq * 2;
            float* Cp = C + (size_t)row0 * N + col;
            Cp[0] = acc[mi][ni][0];
            Cp[1] = acc[mi][ni][1];
            float* Cq = C + (size_t)(row0 + 8) * N + col;
            Cq[0] = acc[mi][ni][2];
            Cq[1] = acc[mi][ni][3];
        }
    }
}

// ============================================================
// Flash attention (causal, GQA) — tf32 mma, online softmax,
// cp.async double-buffered K/V tiles.
// one CTA per (qtile=64, head, batch)
// ============================================================
#define ATQ 64
#define ATK 64
#define QLD 136
#define SLD 68

// Qs + 2*(Ks+Vs) + Ss + stats
#define ATT_SMEM ((5 * ATQ * QLD + ATQ * SLD + 3 * ATQ) * 4)

__global__ __launch_bounds__(256, 1)
void attn_kernel(const float* __restrict__ Q, const float* __restrict__ K,
                 const float* __restrict__ V, float* __restrict__ O)
{
    extern __shared__ float sm[];
    float* Qs  = sm;                     // 64 x 136
    float* Ks0 = Qs  + ATQ * QLD;        // stage 0 K
    float* Vs0 = Ks0 + ATQ * QLD;        // stage 0 V
    float* Ks1 = Vs0 + ATQ * QLD;        // stage 1 K
    float* Vs1 = Ks1 + ATQ * QLD;        // stage 1 V
    float* Ss  = Vs1 + ATQ * QLD;        // 64 x 68
    float* rm  = Ss + ATQ * SLD;
    float* rl  = rm + ATQ;
    float* rc  = rl + ATQ;

    const int tid  = threadIdx.x;
    const int lane = tid & 31;
    const int w    = tid >> 5;
    const int qt = blockIdx.x, h = blockIdx.y, b = blockIdx.z;
    const int q0 = qt * ATQ;
    const int kvh = h >> 2;

    const float* Qg = Q + ((size_t)(b * TT + q0)) * DM + h * DK;
    const float* Kg = K + (size_t)(b * TT) * (NKV * DK) + kvh * DK;
    const float* Vg = V + (size_t)(b * TT) * (NKV * DK) + kvh * DK;

    // async-load a K/V tile pair into a stage
    auto issue_tile = [&](int j, int st) {
        const float* Kt = Kg + (size_t)(j * ATK) * (NKV * DK);
        const float* Vt = Vg + (size_t)(j * ATK) * (NKV * DK);
        float* Kd = st ? Ks1 : Ks0;
        float* Vd = st ? Vs1 : Vs0;
        #pragma unroll
        for (int i = 0; i < 8; i++) {
            const int id = tid + i * 256;
            const int row = id >> 5, c4 = (id & 31) << 2;
            cp16(Kd + row * QLD + c4, Kt + (size_t)row * (NKV * DK) + c4);
            cp16(Vd + row * QLD + c4, Vt + (size_t)row * (NKV * DK) + c4);
        }
        CP_COMMIT();
    };

    issue_tile(0, 0);   // prefetch first tile

    // load Q tile (64 x 128) with regular loads (overlaps cp.async)
    #pragma unroll
    for (int i = 0; i < 8; i++) {
        const int id = tid + i * 256;
        const int row = id >> 5, c4 = (id & 31) << 2;
        *(float4*)(Qs + row * QLD + c4) = *(const float4*)(Qg + (size_t)row * DM + c4);
    }
    if (tid < ATQ) { rm[tid] = -1e30f; rl[tid] = 0.f; }

    float o[8][4];
    #pragma unroll
    for (int i = 0; i < 8; i++)
        #pragma unroll
        for (int j = 0; j < 4; j++) o[i][j] = 0.f;

    const int wq  = (w >> 1) * 16;
    const int wn2 = w & 1;
    const int r  = lane >> 2;
    const int cq = lane & 3;
    const float sscale = 0.08838834764831845f;  // 1/sqrt(128)

    for (int j = 0; j <= qt; j++) {
        const int cur = j & 1;
        if (j < qt) { issue_tile(j + 1, 1 - cur); CP_WAIT1(); }
        else        { CP_WAIT0(); }
        __syncthreads();

        const float* Ksc = cur ? Ks1 : Ks0;
        const float* Vsc = cur ? Vs1 : Vs0;

        // ---- S = Q * K^T (warp: 16q x 32k) ----
        float sacc[4][4];
        #pragma unroll
        for (int i = 0; i < 4; i++)
            #pragma unroll
            for (int k2 = 0; k2 < 4; k2++) sacc[i][k2] = 0.f;

        #pragma unroll
        for (int ks = 0; ks < 16; ks++) {
            const int kb = ks * 8;
            uint32_t af[4];
            const float* p = Qs + (wq + r) * QLD + kb + cq;
            af[0] = ftf(p[0]);
            af[1] = ftf(p[8 * QLD]);
            af[2] = ftf(p[4]);
            af[3] = ftf(p[8 * QLD + 4]);
            #pragma unroll
            for (int ni = 0; ni < 4; ni++) {
                const float* pb = Ksc + (wn2 * 32 + ni * 8 + r) * QLD + kb + cq;
                uint32_t bf[2] = { ftf(pb[0]), ftf(pb[4]) };
                mma_tf32(sacc[ni], af, bf);
            }
        }

        // ---- scale + causal mask + store to Ss ----
        #pragma unroll
        for (int ni = 0; ni < 4; ni++) {
            const int col = wn2 * 32 + ni * 8 + cq * 2;
            const int kg  = j * ATK + col;
            const int rq0 = q0 + wq + r;
            const int rq1 = rq0 + 8;
            float v0 = sacc[ni][0] * sscale; if (kg     > rq0) v0 = -1e30f;
            float v1 = sacc[ni][1] * sscale; if (kg + 1 > rq0) v1 = -1e30f;
            float v2 = sacc[ni][2] * sscale; if (kg     > rq1) v2 = -1e30f;
            float v3 = sacc[ni][3] * sscale; if (kg + 1 > rq1) v3 = -1e30f;
            Ss[(wq + r) * SLD + col]         = v0;
            Ss[(wq + r) * SLD + col + 1]     = v1;
            Ss[(wq + r + 8) * SLD + col]     = v2;
            Ss[(wq + r + 8) * SLD + col + 1] = v3;
        }
        __syncthreads();

        // ---- online softmax (4 threads / row) ----
        {
            const int row = tid >> 2, seg = tid & 3;
            float* Sp = Ss + row * SLD + seg * 16;
            float mx = -1e30f;
            #pragma unroll
            for (int i = 0; i < 16; i++) mx = fmaxf(mx, Sp[i]);
            mx = fmaxf(mx, __shfl_xor_sync(0xffffffffu, mx, 1));
            mx = fmaxf(mx, __shfl_xor_sync(0xffffffffu, mx, 2));
            const float mold = rm[row];
            const float mnew = fmaxf(mold, mx);
            float sum = 0.f;
            #pragma unroll
            for (int i = 0; i < 16; i++) {
                const float p2 = __expf(Sp[i] - mnew);
                Sp[i] = p2;
                sum += p2;
            }
            sum += __shfl_xor_sync(0xffffffffu, sum, 1);
            sum += __shfl_xor_sync(0xffffffffu, sum, 2);
            if (seg == 0) {
                const float corr = __expf(mold - mnew);
                rl[row] = rl[row] * corr + sum;
                rc[row] = corr;
                rm[row] = mnew;
            }
        }
        __syncthreads();

        // ---- rescale O, then O += P * V (warp: 16q x 64d) ----
        {
            const float c0 = rc[wq + r];
            const float c1 = rc[wq + r + 8];
            #pragma unroll
            for (int ni = 0; ni < 8; ni++) {
                o[ni][0] *= c0; o[ni][1] *= c0;
                o[ni][2] *= c1; o[ni][3] *= c1;
            }
        }
        #pragma unroll
        for (int ks = 0; ks < 8; ks++) {
            const int kb = ks * 8;
            uint32_t af[4];
            const float* p = Ss + (wq + r) * SLD + kb + cq;
            af[0] = ftf(p[0]);
            af[1] = ftf(p[8 * SLD]);
            af[2] = ftf(p[4]);
            af[3] = ftf(p[8 * SLD + 4]);
            #pragma unroll
            for (int ni = 0; ni < 8; ni++) {
                const float* pb = Vsc + (kb + cq) * QLD + wn2 * 64 + ni * 8 + r;
                uint32_t bf[2] = { ftf(pb[0]), ftf(pb[4 * QLD]) };
                mma_tf32(o[ni], af, bf);
            }
        }
        __syncthreads();
    }

    // ---- normalize + write out ----
    const float inv0 = 1.f / rl[wq + r];
    const float inv1 = 1.f / rl[wq + r + 8];
    #pragma unroll
    for (int ni = 0; ni < 8; ni++) {
        const int col = h * DK + wn2 * 64 + ni * 8 + cq * 2;
        const size_t row0 = (size_t)(b * TT + q0 + wq + r);
        O[row0 * DM + col]           = o[ni][0] * inv0;
        O[row0 * DM + col + 1]       = o[ni][1] * inv0;
        O[(row0 + 8) * DM + col]     = o[ni][2] * inv1;
        O[(row0 + 8) * DM + col + 1] = o[ni][3] * inv1;
    }
}

// ============================================================
// launch
// ============================================================
extern "C" void kernel_launch(void* const* d_in, const int* in_sizes, int n_in,
                              void* d_out, int out_size)
{
    const float* x  = (const float*)d_in[0];
    const float* wq = (const float*)d_in[1];
    const float* wk = (const float*)d_in[2];
    const float* wv = (const float*)d_in[3];
    const float* wo = (const float*)d_in[4];
    float* out = (float*)d_out;

    void *pQ, *pK, *pV, *pO, *pWQ, *pWK;
    cudaGetSymbolAddress(&pQ, g_Q);
    cudaGetSymbolAddress(&pK, g_K);
    cudaGetSymbolAddress(&pV, g_V);
    cudaGetSymbolAddress(&pO, g_O);
    cudaGetSymbolAddress(&pWQ, g_WQ);
    cudaGetSymbolAddress(&pWK, g_WK);
    float* gQ  = (float*)pQ;
    float* gK  = (float*)pK;
    float* gV  = (float*)pV;
    float* gO  = (float*)pO;
    float* gWQ = (float*)pWQ;
    float* gWK = (float*)pWK;

    cudaFuncSetAttribute(attn_kernel, cudaFuncAttributeMaxDynamicSharedMemorySize, ATT_SMEM);

    const int M = BB * TT;  // 4096

    // Fold RoPE into the weights (idx = h*64*DM + d*DM + k)
    rot_weights<<<(NH  * 64 * DM) / 256, 256>>>(wq, gWQ);
    rot_weights<<<(NKV * 64 * DM) / 256, 256>>>(wk, gWK);

    // QKV projections (Q/K come out already rotated)
    gemm_nt_tf32<<<dim3(DM / GBN, M / GBM), 256>>>(x, gWQ, gQ, M, DM, DM);
    gemm_nt_tf32<<<dim3((NKV * DK) / GBN, M / GBM), 256>>>(x, gWK, gK, M, NKV * DK, DM);
    gemm_nt_tf32<<<dim3((NKV * DK) / GBN, M / GBM), 256>>>(x, wv, gV, M, NKV * DK, DM);

    // Attention
    attn_kernel<<<dim3(TT / ATQ, NH, BB), 256, ATT_SMEM>>>(gQ, gK, gV, gO);

    // Output projection
    gemm_nt_tf32<<<dim3(DM / GBN, M / GBM), 256>>>(gO, wo, out, M, DM, DM);
}